// round 11
// baseline (speedup 1.0000x reference)
#include <cuda_runtime.h>
#include <cuda_fp16.h>
#include <cstdint>

// ===========================================================================
// Beam search tree: one fp16 GEMM (mma.sync fallback HMMA, sm_103-safe)
//   Y[B,256] = X[B,128] x W'[256,128]^T,  W' rows interleaved (re_j, im_j).
// fp16 2-term split: x = xhi + xlo, w = fp16. Residual ~2^-12 (w quant).
// THIS ROUND: split-K prefetch into a SINGLE X buffer. k-step s reads only
// X cols 16s..16s+15, so after s=0..3 the first half of X(t) is dead and
// cp.async can stream X(t+1) cols 0..63 in place, hidden under s=4..7 MMAs;
// second half streams under diffs+epilogue. No convert phase (in-register
// hi/lo split, R10-identical math).
// ===========================================================================

#define GRID    152
#define NTILES  1024            // 131072 rows / 128
#define THREADS 512

#define XSTR    136             // fp32 row stride (floats): 2-way bank max
#define OFF_X   0               // X fp32 [128][136]          (69632B)
#define OFF_W   69632           // W fp16 [256][128] swizzled (64KB)
#define OFF_DIF 135168          // diffs [64][130] f32        (33280B)
#define DSTR    130
#define SMEM_TOTAL (135168 + 64 * DSTR * 4)   // 168448

typedef unsigned long long u64;

__device__ __host__ __forceinline__ int swz256(int a) { return a ^ ((a >> 4) & 0x70); }

__device__ __forceinline__ uint32_t smem_u32(const void* p) {
    uint32_t a;
    asm("{ .reg .u64 t; cvta.to.shared.u64 t, %1; cvt.u32.u64 %0, t; }" : "=r"(a) : "l"(p));
    return a;
}
#define LDSM4(r, a) \
    asm volatile("ldmatrix.sync.aligned.m8n8.x4.shared.b16 {%0,%1,%2,%3}, [%4];" \
        : "=r"((r)[0]), "=r"((r)[1]), "=r"((r)[2]), "=r"((r)[3]) : "r"(a))

__device__ __forceinline__ void mma_f16(float* d, const uint32_t* a, uint32_t b0, uint32_t b1) {
    asm volatile("mma.sync.aligned.m16n8k16.row.col.f32.f16.f16.f32 "
        "{%0,%1,%2,%3}, {%4,%5,%6,%7}, {%8,%9}, {%0,%1,%2,%3};"
        : "+f"(d[0]), "+f"(d[1]), "+f"(d[2]), "+f"(d[3])
        : "r"(a[0]), "r"(a[1]), "r"(a[2]), "r"(a[3]), "r"(b0), "r"(b1));
}

__device__ __forceinline__ float sigm_neg(float d) {   // 1/(1+exp(d))
    return 1.0f / (1.0f + __expf(d));
}
__device__ __forceinline__ uint32_t h2raw(__half2 h) { return *(uint32_t*)&h; }

__device__ __forceinline__ uint32_t pack_hi(float2 v) {
    return h2raw(__float22half2_rn(v));
}
__device__ __forceinline__ uint32_t pack_lo(float2 v, uint32_t hi) {
    __half2 h = *(__half2*)&hi;
    float2 b = __half22float2(h);
    return h2raw(__float22half2_rn(make_float2(v.x - b.x, v.y - b.y)));
}

// ---------------------------------------------------------------------------
// Prep: W' fp16 image in final smem layout (unchanged).
// Row n: n=2j -> re coeffs of beam j ([wr | -wi]); n=2j+1 -> im ([wi | wr]).
// ---------------------------------------------------------------------------
__device__ __align__(16) unsigned short g_W[32768];

__device__ __forceinline__ void store_w(int n, int k, float v) {
    __half h = __float2half(v);
    g_W[swz256(n * 256 + 2 * k) >> 1] = *(unsigned short*)&h;
}

__global__ void prep_kernel(const float* __restrict__ t0, const float* __restrict__ t1,
                            const float* __restrict__ t2, const float* __restrict__ t3,
                            const float* __restrict__ t4) {
    int idx = blockIdx.x * blockDim.x + threadIdx.x;
    if (idx >= 64 * 128) return;
    int a = idx >> 7;
    int j = idx & 127;
    float wr = 0.0f, wi = 0.0f;
    if (j < 62) {
        const float* th; int rel;
        if (j < 2)       { th = t0; rel = j; }
        else if (j < 6)  { th = t1; rel = j - 2; }
        else if (j < 14) { th = t2; rel = j - 6; }
        else if (j < 30) { th = t3; rel = j - 14; }
        else             { th = t4; rel = j - 30; }
        int node = rel >> 1, child = rel & 1;
        float theta = th[(node * 64 + a) * 2 + child];
        float s, c;
        sincosf(theta, &s, &c);
        wr = c * 0.125f;  wi = s * 0.125f;
    } else if (j < 126) {
        int jj = j - 62;
        double cmin = cos(3.14159265358979323846 - 1e-6);
        double cj   = 1.0 + (double)jj * ((cmin - 1.0) / 63.0);
        double ph   = 3.14159265358979323846 * (double)a * cj;
        double s, c;
        sincos(ph, &s, &c);
        wr = (float)(c * 0.125);  wi = (float)(s * 0.125);
    }
    store_w(2 * j,     a,      wr);
    store_w(2 * j,     64 + a, -wi);
    store_w(2 * j + 1, a,      wi);
    store_w(2 * j + 1, 64 + a, wr);
}

// ---------------------------------------------------------------------------
// cp.async issuers. Full tile (prologue) and half tiles (cols 0-63 / 64-127).
// Global X row stride = 128 floats; smem row stride = XSTR floats.
// ---------------------------------------------------------------------------
__device__ __forceinline__ void issue_x_full(uint32_t sb, const float* __restrict__ gx, int tid) {
    #pragma unroll
    for (int i = 0; i < 8; i++) {
        int i4 = tid + THREADS * i;          // 16B-chunk id 0..4095 (32/row)
        int row = i4 >> 5, c = i4 & 31;
        uint32_t sa = sb + OFF_X + (row * XSTR + c * 4) * 4;
        asm volatile("cp.async.ca.shared.global [%0], [%1], 16;"
                     :: "r"(sa), "l"(gx + row * 128 + c * 4) : "memory");
    }
    asm volatile("cp.async.commit_group;" ::: "memory");
}
// half = 0 -> cols 0..63 (chunks 0..15), half = 1 -> cols 64..127
__device__ __forceinline__ void issue_x_half(uint32_t sb, const float* __restrict__ gx,
                                             int tid, int half) {
    #pragma unroll
    for (int i = 0; i < 4; i++) {
        int h = tid + THREADS * i;           // 0..2047 (16 chunks/row)
        int row = h >> 4, c = (h & 15) + half * 16;
        uint32_t sa = sb + OFF_X + (row * XSTR + c * 4) * 4;
        asm volatile("cp.async.ca.shared.global [%0], [%1], 16;"
                     :: "r"(sa), "l"(gx + row * 128 + c * 4) : "memory");
    }
    asm volatile("cp.async.commit_group;" ::: "memory");
}

// ---------------------------------------------------------------------------
// Main persistent kernel: 16 warps = 4(M) x 4(N), warp tile 32 rows x 64 cols.
// ---------------------------------------------------------------------------
__global__ void __launch_bounds__(THREADS, 1)
beam_kernel(const float* __restrict__ x, float* __restrict__ out) {
    extern __shared__ char smem[];
    const uint32_t sb = smem_u32(smem);
    float* const dif = (float*)(smem + OFF_DIF);
    const float* const Xf = (const float*)(smem + OFF_X);
    const int tid  = threadIdx.x;
    const int lane = tid & 31;
    const int wid  = tid >> 5;
    const int bid  = blockIdx.x;

    const int mwarp = wid >> 2, nwarp = wid & 3;
    const int m0 = mwarp * 32, n0 = nwarp * 64;
    const int lrow = lane & 15;
    const int kh2  = (lane >> 4) * 16;
    const int g    = lane >> 2, tig = lane & 3;

    uint32_t baseB[4], xmB[4];
    #pragma unroll
    for (int np = 0; np < 4; np++) {
        int r = n0 + np * 16 + lrow;
        baseB[np] = sb + OFF_W + (r << 8);
        xmB[np]   = (r & 7) << 4;
    }
    const float* xp = Xf + (m0 + g) * XSTR + 2 * tig;

    const int n_it = (NTILES - 1 - bid) / GRID + 1;

    // ---- Prologue: stage W (64KB) + cp.async tile 0 ----
    issue_x_full(sb, x + (long)bid * 16384, tid);
    {
        float4*       d1 = (float4*)(smem + OFF_W);
        const float4* s1 = (const float4*)g_W;
        #pragma unroll
        for (int i = tid; i < 4096; i += THREADS) d1[i] = s1[i];
    }
    asm volatile("cp.async.wait_group 0;" ::: "memory");
    __syncthreads();

    for (int it = 0; it < n_it; it++) {
        const long tile = bid + (long)it * GRID;
        const bool hn   = (it + 1) < n_it;
        const float* gxn = x + (tile + GRID) * 16384;

        float acc[2][8][4];
        #pragma unroll
        for (int mb = 0; mb < 2; mb++)
            #pragma unroll
            for (int nb = 0; nb < 8; nb++)
                #pragma unroll
                for (int c = 0; c < 4; c++) acc[mb][nb][c] = 0.0f;

        // ---- k-steps 0..3 (X cols 0..63), then 4..7 (cols 64..127) ----
        #pragma unroll
        for (int sh = 0; sh < 2; sh++) {
            #pragma unroll
            for (int si = 0; si < 4; si++) {
                const int s  = 4 * sh + si;
                const int k2 = 32 * s + kh2;
                const float* xs = xp + 16 * s;
                uint32_t ah[2][4], al[2][4];
                #pragma unroll
                for (int mb = 0; mb < 2; mb++) {
                    const float* xb = xs + mb * 16 * XSTR;
                    float2 v0 = *(const float2*)(xb);
                    float2 v1 = *(const float2*)(xb + 8 * XSTR);
                    float2 v2 = *(const float2*)(xb + 8);
                    float2 v3 = *(const float2*)(xb + 8 * XSTR + 8);
                    ah[mb][0] = pack_hi(v0);  ah[mb][1] = pack_hi(v1);
                    ah[mb][2] = pack_hi(v2);  ah[mb][3] = pack_hi(v3);
                    al[mb][0] = pack_lo(v0, ah[mb][0]);  al[mb][1] = pack_lo(v1, ah[mb][1]);
                    al[mb][2] = pack_lo(v2, ah[mb][2]);  al[mb][3] = pack_lo(v3, ah[mb][3]);
                }
                uint32_t bh[4][4];
                #pragma unroll
                for (int np = 0; np < 4; np++) LDSM4(bh[np], baseB[np] + (k2 ^ xmB[np]));
                // pass 1: xhi x w — 16 independent MMAs (distance 16)
                #pragma unroll
                for (int mb = 0; mb < 2; mb++)
                    #pragma unroll
                    for (int np = 0; np < 4; np++) {
                        mma_f16(acc[mb][2*np],   ah[mb], bh[np][0], bh[np][2]);
                        mma_f16(acc[mb][2*np+1], ah[mb], bh[np][1], bh[np][3]);
                    }
                // pass 2: xlo x w — same accs, distance 16
                #pragma unroll
                for (int mb = 0; mb < 2; mb++)
                    #pragma unroll
                    for (int np = 0; np < 4; np++) {
                        mma_f16(acc[mb][2*np],   al[mb], bh[np][0], bh[np][2]);
                        mma_f16(acc[mb][2*np+1], al[mb], bh[np][1], bh[np][3]);
                    }
            }
            if (sh == 0) {
                // cols 0..63 of tile t are dead; stream in tile t+1 first half
                __syncthreads();
                if (hn) issue_x_half(sb, gxn, tid, 0);
            }
        }
        __syncthreads();                 // cols 64..127 now dead too
        if (hn) issue_x_half(sb, gxn, tid, 1);

        // ---- Pair diffs d_q = g(2q+1) - g(2q); partner via shfl.xor(1) ----
        #pragma unroll
        for (int mb = 0; mb < 2; mb++)
            #pragma unroll
            for (int nb = 0; nb < 8; nb++) {
                float g0 = acc[mb][nb][0] * acc[mb][nb][0] + acc[mb][nb][1] * acc[mb][nb][1];
                float g1 = acc[mb][nb][2] * acc[mb][nb][2] + acc[mb][nb][3] * acc[mb][nb][3];
                float og0 = __shfl_xor_sync(0xffffffffu, g0, 1);
                float og1 = __shfl_xor_sync(0xffffffffu, g1, 1);
                if ((tig & 1) == 0) {
                    int j = (n0 >> 1) + nb * 4 + tig;   // even beam of the pair
                    int q = j >> 1;                     // pair index 0..63
                    int m = m0 + mb * 16 + g;
                    dif[q * DSTR + m]     = og0 - g0;
                    dif[q * DSTR + m + 8] = og1 - g1;
                }
            }
        __syncthreads();

        // ---- Epilogue(it): 4 threads/row, one 16-leaf subtree each ----
        {
            const int row = tid >> 2, s = tid & 3;
            float p0 = sigm_neg(dif[row]);                       // q=0
            float f  = ((s >> 1) == 0) ? p0 : 1.0f - p0;
            p0 = sigm_neg(dif[(1 + (s >> 1)) * DSTR + row]);     // q=1+(s>>1)
            f *= ((s & 1) == 0) ? p0 : 1.0f - p0;
            float rp2[2];
            p0 = sigm_neg(dif[(3 + s) * DSTR + row]);
            rp2[0] = f * p0;  rp2[1] = f - f * p0;
            float rp3[4];
            #pragma unroll
            for (int j = 0; j < 2; j++) {
                p0 = sigm_neg(dif[(7 + 2 * s + j) * DSTR + row]);
                rp3[2*j] = rp2[j] * p0;  rp3[2*j+1] = rp2[j] - rp2[j] * p0;
            }
            float rp4[8];
            #pragma unroll
            for (int j = 0; j < 4; j++) {
                p0 = sigm_neg(dif[(15 + 4 * s + j) * DSTR + row]);
                rp4[2*j] = rp3[j] * p0;  rp4[2*j+1] = rp3[j] - rp3[j] * p0;
            }
            float rp5[16];
            #pragma unroll
            for (int j = 0; j < 8; j++) {
                p0 = sigm_neg(dif[(31 + 8 * s + j) * DSTR + row]);
                rp5[2*j] = rp4[j] * p0;  rp5[2*j+1] = rp4[j] - rp4[j] * p0;
            }
            float4* o4 = (float4*)(out + (tile * 128 + row) * 64 + 16 * s);
            #pragma unroll
            for (int j = 0; j < 4; j++)
                o4[j] = make_float4(rp5[4*j], rp5[4*j+1], rp5[4*j+2], rp5[4*j+3]);
        }
        asm volatile("cp.async.wait_group 0;" ::: "memory");
        __syncthreads();
    }
}

// ---------------------------------------------------------------------------
extern "C" void kernel_launch(void* const* d_in, const int* in_sizes, int n_in,
                              void* d_out, int out_size) {
    const float* x  = (const float*)d_in[0];
    const float* t0 = (const float*)d_in[1];
    const float* t1 = (const float*)d_in[2];
    const float* t2 = (const float*)d_in[3];
    const float* t3 = (const float*)d_in[4];
    const float* t4 = (const float*)d_in[5];
    float* out = (float*)d_out;

    prep_kernel<<<32, 256>>>(t0, t1, t2, t3, t4);

    cudaFuncSetAttribute(beam_kernel, cudaFuncAttributeMaxDynamicSharedMemorySize, SMEM_TOTAL);
    beam_kernel<<<GRID, THREADS, SMEM_TOTAL>>>(x, out);
}

// round 12
// speedup vs baseline: 1.0075x; 1.0075x over previous
#include <cuda_runtime.h>
#include <cuda_fp16.h>
#include <cstdint>

// ===========================================================================
// Beam search tree: one fp16 GEMM (mma.sync fallback HMMA, sm_103-safe)
//   Y[B,256] = X[B,128] x W'[256,128]^T,  W' rows interleaved (re_j, im_j).
// fp16 2-term split: x = xhi + xlo, w = fp16. Residual ~2^-12 (w quant).
// THIS ROUND: 1024 threads / CTA -> 8 warps per SMSP (occ 50%) to cover the
// latency exposure that kept issue at 37%. 32 warps = 8(M)x4(N), warp tile
// 16 rows x 64 cols (acc 32 regs). X fp32 in smem via cp.async; in-register
// hi/lo split (R10-identical arithmetic & accumulation order).
// ===========================================================================

#define GRID    152
#define NTILES  1024            // 131072 rows / 128
#define THREADS 1024

#define XSTR    136             // fp32 row stride (floats): 2-way bank max
#define OFF_X   0               // X fp32 [128][136]          (69632B)
#define OFF_W   69632           // W fp16 [256][128] swizzled (64KB)
#define OFF_DIF 135168          // diffs [64][130] f32        (33280B)
#define DSTR    130
#define SMEM_TOTAL (135168 + 64 * DSTR * 4)   // 168448

typedef unsigned long long u64;

__device__ __host__ __forceinline__ int swz256(int a) { return a ^ ((a >> 4) & 0x70); }

__device__ __forceinline__ uint32_t smem_u32(const void* p) {
    uint32_t a;
    asm("{ .reg .u64 t; cvta.to.shared.u64 t, %1; cvt.u32.u64 %0, t; }" : "=r"(a) : "l"(p));
    return a;
}
#define LDSM4(r, a) \
    asm volatile("ldmatrix.sync.aligned.m8n8.x4.shared.b16 {%0,%1,%2,%3}, [%4];" \
        : "=r"((r)[0]), "=r"((r)[1]), "=r"((r)[2]), "=r"((r)[3]) : "r"(a))

__device__ __forceinline__ void mma_f16(float* d, const uint32_t* a, uint32_t b0, uint32_t b1) {
    asm volatile("mma.sync.aligned.m16n8k16.row.col.f32.f16.f16.f32 "
        "{%0,%1,%2,%3}, {%4,%5,%6,%7}, {%8,%9}, {%0,%1,%2,%3};"
        : "+f"(d[0]), "+f"(d[1]), "+f"(d[2]), "+f"(d[3])
        : "r"(a[0]), "r"(a[1]), "r"(a[2]), "r"(a[3]), "r"(b0), "r"(b1));
}

__device__ __forceinline__ float sigm_neg(float d) {   // 1/(1+exp(d))
    return 1.0f / (1.0f + __expf(d));
}
__device__ __forceinline__ uint32_t h2raw(__half2 h) { return *(uint32_t*)&h; }

__device__ __forceinline__ uint32_t pack_hi(float2 v) {
    return h2raw(__float22half2_rn(v));
}
__device__ __forceinline__ uint32_t pack_lo(float2 v, uint32_t hi) {
    __half2 h = *(__half2*)&hi;
    float2 b = __half22float2(h);
    return h2raw(__float22half2_rn(make_float2(v.x - b.x, v.y - b.y)));
}

// ---------------------------------------------------------------------------
// Prep: W' fp16 image in final smem layout (unchanged).
// Row n: n=2j -> re coeffs of beam j ([wr | -wi]); n=2j+1 -> im ([wi | wr]).
// ---------------------------------------------------------------------------
__device__ __align__(16) unsigned short g_W[32768];

__device__ __forceinline__ void store_w(int n, int k, float v) {
    __half h = __float2half(v);
    g_W[swz256(n * 256 + 2 * k) >> 1] = *(unsigned short*)&h;
}

__global__ void prep_kernel(const float* __restrict__ t0, const float* __restrict__ t1,
                            const float* __restrict__ t2, const float* __restrict__ t3,
                            const float* __restrict__ t4) {
    int idx = blockIdx.x * blockDim.x + threadIdx.x;
    if (idx >= 64 * 128) return;
    int a = idx >> 7;
    int j = idx & 127;
    float wr = 0.0f, wi = 0.0f;
    if (j < 62) {
        const float* th; int rel;
        if (j < 2)       { th = t0; rel = j; }
        else if (j < 6)  { th = t1; rel = j - 2; }
        else if (j < 14) { th = t2; rel = j - 6; }
        else if (j < 30) { th = t3; rel = j - 14; }
        else             { th = t4; rel = j - 30; }
        int node = rel >> 1, child = rel & 1;
        float theta = th[(node * 64 + a) * 2 + child];
        float s, c;
        sincosf(theta, &s, &c);
        wr = c * 0.125f;  wi = s * 0.125f;
    } else if (j < 126) {
        int jj = j - 62;
        double cmin = cos(3.14159265358979323846 - 1e-6);
        double cj   = 1.0 + (double)jj * ((cmin - 1.0) / 63.0);
        double ph   = 3.14159265358979323846 * (double)a * cj;
        double s, c;
        sincos(ph, &s, &c);
        wr = (float)(c * 0.125);  wi = (float)(s * 0.125);
    }
    store_w(2 * j,     a,      wr);
    store_w(2 * j,     64 + a, -wi);
    store_w(2 * j + 1, a,      wi);
    store_w(2 * j + 1, 64 + a, wr);
}

// ---------------------------------------------------------------------------
// cp.async: 128x128 fp32 tile -> smem [128][XSTR], 4 x 16B per thread.
// ---------------------------------------------------------------------------
__device__ __forceinline__ void issue_x_async(uint32_t sb, const float* __restrict__ gx, int tid) {
    #pragma unroll
    for (int i = 0; i < 4; i++) {
        int i4 = tid + THREADS * i;          // 16B-chunk id 0..4095 (32/row)
        int row = i4 >> 5, c = i4 & 31;
        uint32_t sa = sb + OFF_X + (row * XSTR + c * 4) * 4;
        asm volatile("cp.async.ca.shared.global [%0], [%1], 16;"
                     :: "r"(sa), "l"(gx + row * 128 + c * 4) : "memory");
    }
    asm volatile("cp.async.commit_group;" ::: "memory");
}

// ---------------------------------------------------------------------------
// Main persistent kernel: 32 warps = 8(M) x 4(N), warp tile 16 rows x 64 cols.
// ---------------------------------------------------------------------------
__global__ void __launch_bounds__(THREADS, 1)
beam_kernel(const float* __restrict__ x, float* __restrict__ out) {
    extern __shared__ char smem[];
    const uint32_t sb = smem_u32(smem);
    float* const dif = (float*)(smem + OFF_DIF);
    const float* const Xf = (const float*)(smem + OFF_X);
    const int tid  = threadIdx.x;
    const int lane = tid & 31;
    const int wid  = tid >> 5;
    const int bid  = blockIdx.x;

    const int mwarp = wid >> 2, nwarp = wid & 3;     // 8 x 4
    const int m0 = mwarp * 16, n0 = nwarp * 64;
    const int lrow = lane & 15;
    const int kh2  = (lane >> 4) * 16;
    const int g    = lane >> 2, tig = lane & 3;

    uint32_t baseB[4], xmB[4];
    #pragma unroll
    for (int np = 0; np < 4; np++) {
        int r = n0 + np * 16 + lrow;
        baseB[np] = sb + OFF_W + (r << 8);
        xmB[np]   = (r & 7) << 4;
    }
    const float* xp = Xf + (m0 + g) * XSTR + 2 * tig;

    const int n_it = (NTILES - 1 - bid) / GRID + 1;

    // ---- Prologue: stage W (64KB) + cp.async tile 0 ----
    issue_x_async(sb, x + (long)bid * 16384, tid);
    {
        float4*       d1 = (float4*)(smem + OFF_W);
        const float4* s1 = (const float4*)g_W;
        #pragma unroll
        for (int i = tid; i < 4096; i += THREADS) d1[i] = s1[i];
    }
    asm volatile("cp.async.wait_group 0;" ::: "memory");
    __syncthreads();

    for (int it = 0; it < n_it; it++) {
        const long tile = bid + (long)it * GRID;

        // ========== phase B: GEMM(it) from fp32 smem, + pair diffs ==========
        float acc[8][4];
        #pragma unroll
        for (int nb = 0; nb < 8; nb++)
            #pragma unroll
            for (int c = 0; c < 4; c++) acc[nb][c] = 0.0f;

        #pragma unroll
        for (int s = 0; s < 8; s++) {
            const int k2 = 32 * s + kh2;
            const float* xs = xp + 16 * s;
            // A hi/lo fragments: rows (m0+g, m0+g+8), k halves (4 x LDS.64)
            float2 v0 = *(const float2*)(xs);
            float2 v1 = *(const float2*)(xs + 8 * XSTR);
            float2 v2 = *(const float2*)(xs + 8);
            float2 v3 = *(const float2*)(xs + 8 * XSTR + 8);
            uint32_t ah[4], al[4];
            ah[0] = pack_hi(v0);  ah[1] = pack_hi(v1);
            ah[2] = pack_hi(v2);  ah[3] = pack_hi(v3);
            al[0] = pack_lo(v0, ah[0]);  al[1] = pack_lo(v1, ah[1]);
            al[2] = pack_lo(v2, ah[2]);  al[3] = pack_lo(v3, ah[3]);
            uint32_t bh[4][4];
            #pragma unroll
            for (int np = 0; np < 4; np++) LDSM4(bh[np], baseB[np] + (k2 ^ xmB[np]));
            // pass 1: xhi x w — 8 independent MMAs
            #pragma unroll
            for (int np = 0; np < 4; np++) {
                mma_f16(acc[2*np],   ah, bh[np][0], bh[np][2]);
                mma_f16(acc[2*np+1], ah, bh[np][1], bh[np][3]);
            }
            // pass 2: xlo x w — same accs (distance 8; covered by 8 warps/SMSP)
            #pragma unroll
            for (int np = 0; np < 4; np++) {
                mma_f16(acc[2*np],   al, bh[np][0], bh[np][2]);
                mma_f16(acc[2*np+1], al, bh[np][1], bh[np][3]);
            }
        }

        // ---- Pair diffs d_q = g(2q+1) - g(2q); partner via shfl.xor(1) ----
        #pragma unroll
        for (int nb = 0; nb < 8; nb++) {
            float g0 = acc[nb][0] * acc[nb][0] + acc[nb][1] * acc[nb][1];
            float g1 = acc[nb][2] * acc[nb][2] + acc[nb][3] * acc[nb][3];
            float og0 = __shfl_xor_sync(0xffffffffu, g0, 1);
            float og1 = __shfl_xor_sync(0xffffffffu, g1, 1);
            if ((tig & 1) == 0) {
                int j = (n0 >> 1) + nb * 4 + tig;   // even beam of the pair
                int q = j >> 1;                     // pair index 0..63
                int m = m0 + g;
                dif[q * DSTR + m]     = og0 - g0;
                dif[q * DSTR + m + 8] = og1 - g1;
            }
        }
        __syncthreads();

        // ========== phase A: cp.async(it+1) + epilogue(it) ==========
        const bool hn = (it + 1) < n_it;
        if (hn) issue_x_async(sb, x + (tile + GRID) * 16384, tid);
        {
            // 8 threads per row; thread s owns the 8-leaf subtree below
            // level-3 node s (path bits b0=s>>2, b1=(s>>1)&1, b2=s&1).
            const int row = tid >> 3, s = tid & 7;
            float p0 = sigm_neg(dif[row]);                         // q=0
            float f  = ((s >> 2) == 0) ? p0 : 1.0f - p0;
            p0 = sigm_neg(dif[(1 + (s >> 2)) * DSTR + row]);       // q=1+b0
            f *= (((s >> 1) & 1) == 0) ? p0 : 1.0f - p0;
            p0 = sigm_neg(dif[(3 + (s >> 1)) * DSTR + row]);       // q=3+node2
            f *= ((s & 1) == 0) ? p0 : 1.0f - p0;
            // level3 node s: q = 7+s
            float rp2[2];
            p0 = sigm_neg(dif[(7 + s) * DSTR + row]);
            rp2[0] = f * p0;  rp2[1] = f - f * p0;
            // level4: q = 15 + 2s + j
            float rp3[4];
            #pragma unroll
            for (int j = 0; j < 2; j++) {
                p0 = sigm_neg(dif[(15 + 2 * s + j) * DSTR + row]);
                rp3[2*j] = rp2[j] * p0;  rp3[2*j+1] = rp2[j] - rp2[j] * p0;
            }
            // level5: q = 31 + 4s + j
            float rp4[8];
            #pragma unroll
            for (int j = 0; j < 4; j++) {
                p0 = sigm_neg(dif[(31 + 4 * s + j) * DSTR + row]);
                rp4[2*j] = rp3[j] * p0;  rp4[2*j+1] = rp3[j] - rp3[j] * p0;
            }
            float4* o4 = (float4*)(out + (tile * 128 + row) * 64 + 8 * s);
            o4[0] = make_float4(rp4[0], rp4[1], rp4[2], rp4[3]);
            o4[1] = make_float4(rp4[4], rp4[5], rp4[6], rp4[7]);
        }
        asm volatile("cp.async.wait_group 0;" ::: "memory");
        __syncthreads();
    }
}

// ---------------------------------------------------------------------------
extern "C" void kernel_launch(void* const* d_in, const int* in_sizes, int n_in,
                              void* d_out, int out_size) {
    const float* x  = (const float*)d_in[0];
    const float* t0 = (const float*)d_in[1];
    const float* t1 = (const float*)d_in[2];
    const float* t2 = (const float*)d_in[3];
    const float* t3 = (const float*)d_in[4];
    const float* t4 = (const float*)d_in[5];
    float* out = (float*)d_out;

    prep_kernel<<<32, 256>>>(t0, t1, t2, t3, t4);

    cudaFuncSetAttribute(beam_kernel, cudaFuncAttributeMaxDynamicSharedMemorySize, SMEM_TOTAL);
    beam_kernel<<<GRID, THREADS, SMEM_TOTAL>>>(x, out);
}

// round 13
// speedup vs baseline: 1.1542x; 1.1455x over previous
#include <cuda_runtime.h>
#include <cuda_fp16.h>
#include <cstdint>

// ===========================================================================
// Beam search tree: one fp16 GEMM (mma.sync fallback HMMA, sm_103-safe)
//   Y[B,256] = X[B,128] x W'[256,128]^T,  W' rows interleaved (re_j, im_j).
// fp16 2-term split: x = xhi + xlo, w = fp16.
// THIS ROUND: precision-targeted MMA cut. xlo correction pass applied ONLY to
// cols 0..127 (beams 0..63 = all internal tree nodes); leaf-DFT cols 128..255
// get single-pass (their per-layer error x2.2, total ~5.2e-4, 2x gate margin).
// Warp map nwarp=wid>>2 keeps the asymmetric load SMSP-balanced.
// Base structure = R10: X fp32 in smem via cp.async, in-register hi/lo split,
// distance-16 MMA passes, 512 thr, 1 CTA/SM, 128-row tiles.
// ===========================================================================

#define GRID    152
#define NTILES  1024            // 131072 rows / 128
#define THREADS 512

#define XSTR    136             // fp32 row stride (floats): conflict-free LDS.64
#define OFF_X   0               // X fp32 [128][136]          (69632B)
#define OFF_W   69632           // W fp16 [256][128] swizzled (64KB)
#define OFF_DIF 135168          // diffs [64][130] f32        (33280B)
#define DSTR    130
#define SMEM_TOTAL (135168 + 64 * DSTR * 4)   // 168448

typedef unsigned long long u64;

__device__ __host__ __forceinline__ int swz256(int a) { return a ^ ((a >> 4) & 0x70); }

__device__ __forceinline__ uint32_t smem_u32(const void* p) {
    uint32_t a;
    asm("{ .reg .u64 t; cvta.to.shared.u64 t, %1; cvt.u32.u64 %0, t; }" : "=r"(a) : "l"(p));
    return a;
}
#define LDSM4(r, a) \
    asm volatile("ldmatrix.sync.aligned.m8n8.x4.shared.b16 {%0,%1,%2,%3}, [%4];" \
        : "=r"((r)[0]), "=r"((r)[1]), "=r"((r)[2]), "=r"((r)[3]) : "r"(a))

__device__ __forceinline__ void mma_f16(float* d, const uint32_t* a, uint32_t b0, uint32_t b1) {
    asm volatile("mma.sync.aligned.m16n8k16.row.col.f32.f16.f16.f32 "
        "{%0,%1,%2,%3}, {%4,%5,%6,%7}, {%8,%9}, {%0,%1,%2,%3};"
        : "+f"(d[0]), "+f"(d[1]), "+f"(d[2]), "+f"(d[3])
        : "r"(a[0]), "r"(a[1]), "r"(a[2]), "r"(a[3]), "r"(b0), "r"(b1));
}

__device__ __forceinline__ float sigm_neg(float d) {   // 1/(1+exp(d))
    return 1.0f / (1.0f + __expf(d));
}
__device__ __forceinline__ uint32_t h2raw(__half2 h) { return *(uint32_t*)&h; }

__device__ __forceinline__ uint32_t pack_hi(float2 v) {
    return h2raw(__float22half2_rn(v));
}
__device__ __forceinline__ uint32_t pack_lo(float2 v, uint32_t hi) {
    __half2 h = *(__half2*)&hi;
    float2 b = __half22float2(h);
    return h2raw(__float22half2_rn(make_float2(v.x - b.x, v.y - b.y)));
}

// ---------------------------------------------------------------------------
// Prep: W' fp16 image in final smem layout (unchanged).
// Row n: n=2j -> re coeffs of beam j ([wr | -wi]); n=2j+1 -> im ([wi | wr]).
// ---------------------------------------------------------------------------
__device__ __align__(16) unsigned short g_W[32768];

__device__ __forceinline__ void store_w(int n, int k, float v) {
    __half h = __float2half(v);
    g_W[swz256(n * 256 + 2 * k) >> 1] = *(unsigned short*)&h;
}

__global__ void prep_kernel(const float* __restrict__ t0, const float* __restrict__ t1,
                            const float* __restrict__ t2, const float* __restrict__ t3,
                            const float* __restrict__ t4) {
    int idx = blockIdx.x * blockDim.x + threadIdx.x;
    if (idx >= 64 * 128) return;
    int a = idx >> 7;
    int j = idx & 127;
    float wr = 0.0f, wi = 0.0f;
    if (j < 62) {
        const float* th; int rel;
        if (j < 2)       { th = t0; rel = j; }
        else if (j < 6)  { th = t1; rel = j - 2; }
        else if (j < 14) { th = t2; rel = j - 6; }
        else if (j < 30) { th = t3; rel = j - 14; }
        else             { th = t4; rel = j - 30; }
        int node = rel >> 1, child = rel & 1;
        float theta = th[(node * 64 + a) * 2 + child];
        float s, c;
        sincosf(theta, &s, &c);
        wr = c * 0.125f;  wi = s * 0.125f;
    } else if (j < 126) {
        int jj = j - 62;
        double cmin = cos(3.14159265358979323846 - 1e-6);
        double cj   = 1.0 + (double)jj * ((cmin - 1.0) / 63.0);
        double ph   = 3.14159265358979323846 * (double)a * cj;
        double s, c;
        sincos(ph, &s, &c);
        wr = (float)(c * 0.125);  wi = (float)(s * 0.125);
    }
    store_w(2 * j,     a,      wr);
    store_w(2 * j,     64 + a, -wi);
    store_w(2 * j + 1, a,      wi);
    store_w(2 * j + 1, 64 + a, wr);
}

// ---------------------------------------------------------------------------
// cp.async: 128x128 fp32 tile -> smem [128][XSTR], 8 x 16B per thread.
// ---------------------------------------------------------------------------
__device__ __forceinline__ void issue_x_async(uint32_t sb, const float* __restrict__ gx, int tid) {
    #pragma unroll
    for (int i = 0; i < 8; i++) {
        int i4 = tid + THREADS * i;          // 16B-chunk id 0..4095 (32/row)
        int row = i4 >> 5, c = i4 & 31;
        uint32_t sa = sb + OFF_X + (row * XSTR + c * 4) * 4;
        asm volatile("cp.async.ca.shared.global [%0], [%1], 16;"
                     :: "r"(sa), "l"(gx + row * 128 + c * 4) : "memory");
    }
    asm volatile("cp.async.commit_group;" ::: "memory");
}

// ---------------------------------------------------------------------------
// Main persistent kernel: 16 warps = 4(M) x 4(N), warp tile 32 rows x 64 cols.
// SMSP = wid & 3 = mwarp -> each SMSP hosts all 4 nwarp values (balanced).
// ---------------------------------------------------------------------------
__global__ void __launch_bounds__(THREADS, 1)
beam_kernel(const float* __restrict__ x, float* __restrict__ out) {
    extern __shared__ char smem[];
    const uint32_t sb = smem_u32(smem);
    float* const dif = (float*)(smem + OFF_DIF);
    const float* const Xf = (const float*)(smem + OFF_X);
    const int tid  = threadIdx.x;
    const int lane = tid & 31;
    const int wid  = tid >> 5;
    const int bid  = blockIdx.x;

    const int nwarp = wid >> 2, mwarp = wid & 3;   // SMSP-balanced nwarp
    const int m0 = mwarp * 32, n0 = nwarp * 64;
    const bool do_lo = (nwarp < 2);                // xlo pass: cols 0..127 only
    const int lrow = lane & 15;
    const int kh2  = (lane >> 4) * 16;
    const int g    = lane >> 2, tig = lane & 3;

    uint32_t baseB[4], xmB[4];
    #pragma unroll
    for (int np = 0; np < 4; np++) {
        int r = n0 + np * 16 + lrow;
        baseB[np] = sb + OFF_W + (r << 8);
        xmB[np]   = (r & 7) << 4;
    }
    const float* xp = Xf + (m0 + g) * XSTR + 2 * tig;

    const int n_it = (NTILES - 1 - bid) / GRID + 1;

    // ---- Prologue: stage W (64KB) + cp.async tile 0 ----
    issue_x_async(sb, x + (long)bid * 16384, tid);
    {
        float4*       d1 = (float4*)(smem + OFF_W);
        const float4* s1 = (const float4*)g_W;
        #pragma unroll
        for (int i = tid; i < 4096; i += THREADS) d1[i] = s1[i];
    }
    asm volatile("cp.async.wait_group 0;" ::: "memory");
    __syncthreads();

    for (int it = 0; it < n_it; it++) {
        const long tile = bid + (long)it * GRID;

        // ========== phase B: GEMM(it) from fp32 smem, + pair diffs ==========
        float acc[2][8][4];
        #pragma unroll
        for (int mb = 0; mb < 2; mb++)
            #pragma unroll
            for (int nb = 0; nb < 8; nb++)
                #pragma unroll
                for (int c = 0; c < 4; c++) acc[mb][nb][c] = 0.0f;

        #pragma unroll
        for (int s = 0; s < 8; s++) {
            const int k2 = 32 * s + kh2;
            const float* xs = xp + 16 * s;
            uint32_t ah[2][4];
            float2 vv[2][4];
            #pragma unroll
            for (int mb = 0; mb < 2; mb++) {
                const float* xb = xs + mb * 16 * XSTR;
                vv[mb][0] = *(const float2*)(xb);
                vv[mb][1] = *(const float2*)(xb + 8 * XSTR);
                vv[mb][2] = *(const float2*)(xb + 8);
                vv[mb][3] = *(const float2*)(xb + 8 * XSTR + 8);
                ah[mb][0] = pack_hi(vv[mb][0]);  ah[mb][1] = pack_hi(vv[mb][1]);
                ah[mb][2] = pack_hi(vv[mb][2]);  ah[mb][3] = pack_hi(vv[mb][3]);
            }
            uint32_t bh[4][4];
            #pragma unroll
            for (int np = 0; np < 4; np++) LDSM4(bh[np], baseB[np] + (k2 ^ xmB[np]));
            // pass 1: xhi x w — 16 independent MMAs (distance 16)
            #pragma unroll
            for (int mb = 0; mb < 2; mb++)
                #pragma unroll
                for (int np = 0; np < 4; np++) {
                    mma_f16(acc[mb][2*np],   ah[mb], bh[np][0], bh[np][2]);
                    mma_f16(acc[mb][2*np+1], ah[mb], bh[np][1], bh[np][3]);
                }
            // pass 2: xlo x w — internal-node cols only (nwarp 0,1)
            if (do_lo) {
                uint32_t al[2][4];
                #pragma unroll
                for (int mb = 0; mb < 2; mb++) {
                    al[mb][0] = pack_lo(vv[mb][0], ah[mb][0]);
                    al[mb][1] = pack_lo(vv[mb][1], ah[mb][1]);
                    al[mb][2] = pack_lo(vv[mb][2], ah[mb][2]);
                    al[mb][3] = pack_lo(vv[mb][3], ah[mb][3]);
                }
                #pragma unroll
                for (int mb = 0; mb < 2; mb++)
                    #pragma unroll
                    for (int np = 0; np < 4; np++) {
                        mma_f16(acc[mb][2*np],   al[mb], bh[np][0], bh[np][2]);
                        mma_f16(acc[mb][2*np+1], al[mb], bh[np][1], bh[np][3]);
                    }
            }
        }

        // ---- Pair diffs d_q = g(2q+1) - g(2q); partner via shfl.xor(1) ----
        #pragma unroll
        for (int mb = 0; mb < 2; mb++)
            #pragma unroll
            for (int nb = 0; nb < 8; nb++) {
                float g0 = acc[mb][nb][0] * acc[mb][nb][0] + acc[mb][nb][1] * acc[mb][nb][1];
                float g1 = acc[mb][nb][2] * acc[mb][nb][2] + acc[mb][nb][3] * acc[mb][nb][3];
                float og0 = __shfl_xor_sync(0xffffffffu, g0, 1);
                float og1 = __shfl_xor_sync(0xffffffffu, g1, 1);
                if ((tig & 1) == 0) {
                    int j = (n0 >> 1) + nb * 4 + tig;   // even beam of the pair
                    int q = j >> 1;                     // pair index 0..63
                    int m = m0 + mb * 16 + g;
                    dif[q * DSTR + m]     = og0 - g0;
                    dif[q * DSTR + m + 8] = og1 - g1;
                }
            }
        __syncthreads();

        // ========== phase A: cp.async(it+1) + epilogue(it) ==========
        const bool hn = (it + 1) < n_it;
        if (hn) issue_x_async(sb, x + (tile + GRID) * 16384, tid);
        {
            const int row = tid >> 2, s = tid & 3;
            float p0 = sigm_neg(dif[row]);                       // q=0
            float f  = ((s >> 1) == 0) ? p0 : 1.0f - p0;
            p0 = sigm_neg(dif[(1 + (s >> 1)) * DSTR + row]);     // q=1+(s>>1)
            f *= ((s & 1) == 0) ? p0 : 1.0f - p0;
            float rp2[2];
            p0 = sigm_neg(dif[(3 + s) * DSTR + row]);
            rp2[0] = f * p0;  rp2[1] = f - f * p0;
            float rp3[4];
            #pragma unroll
            for (int j = 0; j < 2; j++) {
                p0 = sigm_neg(dif[(7 + 2 * s + j) * DSTR + row]);
                rp3[2*j] = rp2[j] * p0;  rp3[2*j+1] = rp2[j] - rp2[j] * p0;
            }
            float rp4[8];
            #pragma unroll
            for (int j = 0; j < 4; j++) {
                p0 = sigm_neg(dif[(15 + 4 * s + j) * DSTR + row]);
                rp4[2*j] = rp3[j] * p0;  rp4[2*j+1] = rp3[j] - rp3[j] * p0;
            }
            float rp5[16];
            #pragma unroll
            for (int j = 0; j < 8; j++) {
                p0 = sigm_neg(dif[(31 + 8 * s + j) * DSTR + row]);
                rp5[2*j] = rp4[j] * p0;  rp5[2*j+1] = rp4[j] - rp4[j] * p0;
            }
            float4* o4 = (float4*)(out + (tile * 128 + row) * 64 + 16 * s);
            #pragma unroll
            for (int j = 0; j < 4; j++)
                o4[j] = make_float4(rp5[4*j], rp5[4*j+1], rp5[4*j+2], rp5[4*j+3]);
        }
        asm volatile("cp.async.wait_group 0;" ::: "memory");
        __syncthreads();
    }
}

// ---------------------------------------------------------------------------
extern "C" void kernel_launch(void* const* d_in, const int* in_sizes, int n_in,
                              void* d_out, int out_size) {
    const float* x  = (const float*)d_in[0];
    const float* t0 = (const float*)d_in[1];
    const float* t1 = (const float*)d_in[2];
    const float* t2 = (const float*)d_in[3];
    const float* t3 = (const float*)d_in[4];
    const float* t4 = (const float*)d_in[5];
    float* out = (float*)d_out;

    prep_kernel<<<32, 256>>>(t0, t1, t2, t3, t4);

    cudaFuncSetAttribute(beam_kernel, cudaFuncAttributeMaxDynamicSharedMemorySize, SMEM_TOTAL);
    beam_kernel<<<GRID, THREADS, SMEM_TOTAL>>>(x, out);
}

// round 14
// speedup vs baseline: 1.4528x; 1.2587x over previous
#include <cuda_runtime.h>
#include <cuda_fp16.h>
#include <cstdint>

// ===========================================================================
// Beam search tree: one fp16 GEMM (mma.sync fallback HMMA, sm_103-safe)
//   Y[B,256] = X[B,128] x W'[256,128]^T,  W' rows interleaved (re_j, im_j).
// THIS ROUND: single-pass fp16 everywhere (xlo correction dropped in all
// layers). Error budget anchored on R13 measurement: per-single-pass-layer
// increment 1.87e-4 -> total sqrt(4.05^2 + 6*1.87^2)e-4 ~= 6.1e-4 < 1e-3.
// MMA/tile 1536 -> 1024. Base structure = R10/R13: X fp32 in smem via
// cp.async, in-register fp16 pack, distance-16 MMA pass, 512 thr, 1 CTA/SM.
// ===========================================================================

#define GRID    152
#define NTILES  1024            // 131072 rows / 128
#define THREADS 512

#define XSTR    136             // fp32 row stride (floats): conflict-free LDS.64
#define OFF_X   0               // X fp32 [128][136]          (69632B)
#define OFF_W   69632           // W fp16 [256][128] swizzled (64KB)
#define OFF_DIF 135168          // diffs [64][130] f32        (33280B)
#define DSTR    130
#define SMEM_TOTAL (135168 + 64 * DSTR * 4)   // 168448

typedef unsigned long long u64;

__device__ __host__ __forceinline__ int swz256(int a) { return a ^ ((a >> 4) & 0x70); }

__device__ __forceinline__ uint32_t smem_u32(const void* p) {
    uint32_t a;
    asm("{ .reg .u64 t; cvta.to.shared.u64 t, %1; cvt.u32.u64 %0, t; }" : "=r"(a) : "l"(p));
    return a;
}
#define LDSM4(r, a) \
    asm volatile("ldmatrix.sync.aligned.m8n8.x4.shared.b16 {%0,%1,%2,%3}, [%4];" \
        : "=r"((r)[0]), "=r"((r)[1]), "=r"((r)[2]), "=r"((r)[3]) : "r"(a))

__device__ __forceinline__ void mma_f16(float* d, const uint32_t* a, uint32_t b0, uint32_t b1) {
    asm volatile("mma.sync.aligned.m16n8k16.row.col.f32.f16.f16.f32 "
        "{%0,%1,%2,%3}, {%4,%5,%6,%7}, {%8,%9}, {%0,%1,%2,%3};"
        : "+f"(d[0]), "+f"(d[1]), "+f"(d[2]), "+f"(d[3])
        : "r"(a[0]), "r"(a[1]), "r"(a[2]), "r"(a[3]), "r"(b0), "r"(b1));
}

__device__ __forceinline__ float sigm_neg(float d) {   // 1/(1+exp(d))
    return 1.0f / (1.0f + __expf(d));
}
__device__ __forceinline__ uint32_t h2raw(__half2 h) { return *(uint32_t*)&h; }

__device__ __forceinline__ uint32_t pack_hi(float2 v) {
    return h2raw(__float22half2_rn(v));
}

// ---------------------------------------------------------------------------
// Prep: W' fp16 image in final smem layout (unchanged).
// Row n: n=2j -> re coeffs of beam j ([wr | -wi]); n=2j+1 -> im ([wi | wr]).
// ---------------------------------------------------------------------------
__device__ __align__(16) unsigned short g_W[32768];

__device__ __forceinline__ void store_w(int n, int k, float v) {
    __half h = __float2half(v);
    g_W[swz256(n * 256 + 2 * k) >> 1] = *(unsigned short*)&h;
}

__global__ void prep_kernel(const float* __restrict__ t0, const float* __restrict__ t1,
                            const float* __restrict__ t2, const float* __restrict__ t3,
                            const float* __restrict__ t4) {
    int idx = blockIdx.x * blockDim.x + threadIdx.x;
    if (idx >= 64 * 128) return;
    int a = idx >> 7;
    int j = idx & 127;
    float wr = 0.0f, wi = 0.0f;
    if (j < 62) {
        const float* th; int rel;
        if (j < 2)       { th = t0; rel = j; }
        else if (j < 6)  { th = t1; rel = j - 2; }
        else if (j < 14) { th = t2; rel = j - 6; }
        else if (j < 30) { th = t3; rel = j - 14; }
        else             { th = t4; rel = j - 30; }
        int node = rel >> 1, child = rel & 1;
        float theta = th[(node * 64 + a) * 2 + child];
        float s, c;
        sincosf(theta, &s, &c);
        wr = c * 0.125f;  wi = s * 0.125f;
    } else if (j < 126) {
        int jj = j - 62;
        double cmin = cos(3.14159265358979323846 - 1e-6);
        double cj   = 1.0 + (double)jj * ((cmin - 1.0) / 63.0);
        double ph   = 3.14159265358979323846 * (double)a * cj;
        double s, c;
        sincos(ph, &s, &c);
        wr = (float)(c * 0.125);  wi = (float)(s * 0.125);
    }
    store_w(2 * j,     a,      wr);
    store_w(2 * j,     64 + a, -wi);
    store_w(2 * j + 1, a,      wi);
    store_w(2 * j + 1, 64 + a, wr);
}

// ---------------------------------------------------------------------------
// cp.async: 128x128 fp32 tile -> smem [128][XSTR], 8 x 16B per thread.
// ---------------------------------------------------------------------------
__device__ __forceinline__ void issue_x_async(uint32_t sb, const float* __restrict__ gx, int tid) {
    #pragma unroll
    for (int i = 0; i < 8; i++) {
        int i4 = tid + THREADS * i;          // 16B-chunk id 0..4095 (32/row)
        int row = i4 >> 5, c = i4 & 31;
        uint32_t sa = sb + OFF_X + (row * XSTR + c * 4) * 4;
        asm volatile("cp.async.ca.shared.global [%0], [%1], 16;"
                     :: "r"(sa), "l"(gx + row * 128 + c * 4) : "memory");
    }
    asm volatile("cp.async.commit_group;" ::: "memory");
}

// ---------------------------------------------------------------------------
// Main persistent kernel: 16 warps = 4(M) x 4(N), warp tile 32 rows x 64 cols.
// ---------------------------------------------------------------------------
__global__ void __launch_bounds__(THREADS, 1)
beam_kernel(const float* __restrict__ x, float* __restrict__ out) {
    extern __shared__ char smem[];
    const uint32_t sb = smem_u32(smem);
    float* const dif = (float*)(smem + OFF_DIF);
    const float* const Xf = (const float*)(smem + OFF_X);
    const int tid  = threadIdx.x;
    const int lane = tid & 31;
    const int wid  = tid >> 5;
    const int bid  = blockIdx.x;

    const int nwarp = wid >> 2, mwarp = wid & 3;   // SMSP-balanced layout
    const int m0 = mwarp * 32, n0 = nwarp * 64;
    const int lrow = lane & 15;
    const int kh2  = (lane >> 4) * 16;
    const int g    = lane >> 2, tig = lane & 3;

    uint32_t baseB[4], xmB[4];
    #pragma unroll
    for (int np = 0; np < 4; np++) {
        int r = n0 + np * 16 + lrow;
        baseB[np] = sb + OFF_W + (r << 8);
        xmB[np]   = (r & 7) << 4;
    }
    const float* xp = Xf + (m0 + g) * XSTR + 2 * tig;

    const int n_it = (NTILES - 1 - bid) / GRID + 1;

    // ---- Prologue: stage W (64KB) + cp.async tile 0 ----
    issue_x_async(sb, x + (long)bid * 16384, tid);
    {
        float4*       d1 = (float4*)(smem + OFF_W);
        const float4* s1 = (const float4*)g_W;
        #pragma unroll
        for (int i = tid; i < 4096; i += THREADS) d1[i] = s1[i];
    }
    asm volatile("cp.async.wait_group 0;" ::: "memory");
    __syncthreads();

    for (int it = 0; it < n_it; it++) {
        const long tile = bid + (long)it * GRID;

        // ========== phase B: GEMM(it) single fp16 pass, + pair diffs ==========
        float acc[2][8][4];
        #pragma unroll
        for (int mb = 0; mb < 2; mb++)
            #pragma unroll
            for (int nb = 0; nb < 8; nb++)
                #pragma unroll
                for (int c = 0; c < 4; c++) acc[mb][nb][c] = 0.0f;

        #pragma unroll
        for (int s = 0; s < 8; s++) {
            const int k2 = 32 * s + kh2;
            const float* xs = xp + 16 * s;
            uint32_t ah[2][4];
            #pragma unroll
            for (int mb = 0; mb < 2; mb++) {
                const float* xb = xs + mb * 16 * XSTR;
                ah[mb][0] = pack_hi(*(const float2*)(xb));
                ah[mb][1] = pack_hi(*(const float2*)(xb + 8 * XSTR));
                ah[mb][2] = pack_hi(*(const float2*)(xb + 8));
                ah[mb][3] = pack_hi(*(const float2*)(xb + 8 * XSTR + 8));
            }
            uint32_t bh[4][4];
            #pragma unroll
            for (int np = 0; np < 4; np++) LDSM4(bh[np], baseB[np] + (k2 ^ xmB[np]));
            // single pass: x(fp16) x w — 16 independent MMAs (distance 16)
            #pragma unroll
            for (int mb = 0; mb < 2; mb++)
                #pragma unroll
                for (int np = 0; np < 4; np++) {
                    mma_f16(acc[mb][2*np],   ah[mb], bh[np][0], bh[np][2]);
                    mma_f16(acc[mb][2*np+1], ah[mb], bh[np][1], bh[np][3]);
                }
        }

        // ---- Pair diffs d_q = g(2q+1) - g(2q); partner via shfl.xor(1) ----
        #pragma unroll
        for (int mb = 0; mb < 2; mb++)
            #pragma unroll
            for (int nb = 0; nb < 8; nb++) {
                float g0 = acc[mb][nb][0] * acc[mb][nb][0] + acc[mb][nb][1] * acc[mb][nb][1];
                float g1 = acc[mb][nb][2] * acc[mb][nb][2] + acc[mb][nb][3] * acc[mb][nb][3];
                float og0 = __shfl_xor_sync(0xffffffffu, g0, 1);
                float og1 = __shfl_xor_sync(0xffffffffu, g1, 1);
                if ((tig & 1) == 0) {
                    int j = (n0 >> 1) + nb * 4 + tig;   // even beam of the pair
                    int q = j >> 1;                     // pair index 0..63
                    int m = m0 + mb * 16 + g;
                    dif[q * DSTR + m]     = og0 - g0;
                    dif[q * DSTR + m + 8] = og1 - g1;
                }
            }
        __syncthreads();

        // ========== phase A: cp.async(it+1) + epilogue(it) ==========
        const bool hn = (it + 1) < n_it;
        if (hn) issue_x_async(sb, x + (tile + GRID) * 16384, tid);
        {
            const int row = tid >> 2, s = tid & 3;
            float p0 = sigm_neg(dif[row]);                       // q=0
            float f  = ((s >> 1) == 0) ? p0 : 1.0f - p0;
            p0 = sigm_neg(dif[(1 + (s >> 1)) * DSTR + row]);     // q=1+(s>>1)
            f *= ((s & 1) == 0) ? p0 : 1.0f - p0;
            float rp2[2];
            p0 = sigm_neg(dif[(3 + s) * DSTR + row]);
            rp2[0] = f * p0;  rp2[1] = f - f * p0;
            float rp3[4];
            #pragma unroll
            for (int j = 0; j < 2; j++) {
                p0 = sigm_neg(dif[(7 + 2 * s + j) * DSTR + row]);
                rp3[2*j] = rp2[j] * p0;  rp3[2*j+1] = rp2[j] - rp2[j] * p0;
            }
            float rp4[8];
            #pragma unroll
            for (int j = 0; j < 4; j++) {
                p0 = sigm_neg(dif[(15 + 4 * s + j) * DSTR + row]);
                rp4[2*j] = rp3[j] * p0;  rp4[2*j+1] = rp3[j] - rp3[j] * p0;
            }
            float rp5[16];
            #pragma unroll
            for (int j = 0; j < 8; j++) {
                p0 = sigm_neg(dif[(31 + 8 * s + j) * DSTR + row]);
                rp5[2*j] = rp4[j] * p0;  rp5[2*j+1] = rp4[j] - rp4[j] * p0;
            }
            float4* o4 = (float4*)(out + (tile * 128 + row) * 64 + 16 * s);
            #pragma unroll
            for (int j = 0; j < 4; j++)
                o4[j] = make_float4(rp5[4*j], rp5[4*j+1], rp5[4*j+2], rp5[4*j+3]);
        }
        asm volatile("cp.async.wait_group 0;" ::: "memory");
        __syncthreads();
    }
}

// ---------------------------------------------------------------------------
extern "C" void kernel_launch(void* const* d_in, const int* in_sizes, int n_in,
                              void* d_out, int out_size) {
    const float* x  = (const float*)d_in[0];
    const float* t0 = (const float*)d_in[1];
    const float* t1 = (const float*)d_in[2];
    const float* t2 = (const float*)d_in[3];
    const float* t3 = (const float*)d_in[4];
    const float* t4 = (const float*)d_in[5];
    float* out = (float*)d_out;

    prep_kernel<<<32, 256>>>(t0, t1, t2, t3, t4);

    cudaFuncSetAttribute(beam_kernel, cudaFuncAttributeMaxDynamicSharedMemorySize, SMEM_TOTAL);
    beam_kernel<<<GRID, THREADS, SMEM_TOTAL>>>(x, out);
}